// round 7
// baseline (speedup 1.0000x reference)
#include <cuda_runtime.h>
#include <cuda_bf16.h>
#include <cstdint>

#define N_NODES_MAX 100000
#define FEAT 16

__device__ int   g_deg[N_NODES_MAX];   // zero-initialized at load; every call leaves it zeroed
__device__ float g_y[N_NODES_MAX * FEAT];

// ---------------------------------------------------------------------------
// Kernel 1: degree histogram. 16 indices per thread, fire-and-forget
// atomics -> REDG (no return).
// ---------------------------------------------------------------------------
__global__ void hist_kernel(const int4* __restrict__ src4, int E16) {
    int i = blockIdx.x * blockDim.x + threadIdx.x;
    if (i < E16) {
        int4 a = src4[4 * i];
        int4 b = src4[4 * i + 1];
        int4 c = src4[4 * i + 2];
        int4 d = src4[4 * i + 3];
        atomicAdd(&g_deg[a.x], 1); atomicAdd(&g_deg[a.y], 1);
        atomicAdd(&g_deg[a.z], 1); atomicAdd(&g_deg[a.w], 1);
        atomicAdd(&g_deg[b.x], 1); atomicAdd(&g_deg[b.y], 1);
        atomicAdd(&g_deg[b.z], 1); atomicAdd(&g_deg[b.w], 1);
        atomicAdd(&g_deg[c.x], 1); atomicAdd(&g_deg[c.y], 1);
        atomicAdd(&g_deg[c.z], 1); atomicAdd(&g_deg[c.w], 1);
        atomicAdd(&g_deg[d.x], 1); atomicAdd(&g_deg[d.y], 1);
        atomicAdd(&g_deg[d.z], 1); atomicAdd(&g_deg[d.w], 1);
    }
}

// ---------------------------------------------------------------------------
// Kernel 2: per-node precompute  y[n] = (deg[n]-1)*x[n] + extra[n],
// AND reset g_deg[n] = 0 for the next call (replaces the zero kernel).
// The 4 chunk-threads of a node are an aligned quad inside one warp:
// all read deg, __syncwarp, then the quad leader resets it.
// ---------------------------------------------------------------------------
__global__ void compute_y_kernel(const float4* __restrict__ x4,
                                 const float4* __restrict__ e4,
                                 int n4) {
    int i = blockIdx.x * blockDim.x + threadIdx.x;
    if (i < n4) {
        int node = i >> 2;
        int d = g_deg[node];
        __syncwarp();
        if ((i & 3) == 0) g_deg[node] = 0;
        float s = (float)(d - 1);
        float4 xv = x4[i];
        float4 ev = e4[i];
        float4 y;
        y.x = fmaf(s, xv.x, ev.x);
        y.y = fmaf(s, xv.y, ev.y);
        y.z = fmaf(s, xv.z, ev.z);
        y.w = fmaf(s, xv.w, ev.w);
        reinterpret_cast<float4*>(g_y)[i] = y;
    }
}

// ---------------------------------------------------------------------------
// Kernel 3: edge gather, two 4-element batches per thread with src indices
// for BOTH batches prefetched up front. Peak live set ~30 regs (fits the
// 32-reg cap; R5/R6 showed ILP=8 float4 spills). Chain per batch becomes
// gather-latency only; src latency fully hidden.
// Thread t owns elements {t + k*T : k=0..7}, T = total/8. All coalesced.
// ---------------------------------------------------------------------------
__global__ void gather_kernel(const int* __restrict__ src,
                              float4* __restrict__ out4,
                              int T /* = E*4/8 */) {
    int t = blockIdx.x * blockDim.x + threadIdx.x;
    if (t >= T) return;

    const float4* __restrict__ y4 = reinterpret_cast<const float4*>(g_y);

    // Prefetch all 8 src indices (8 independent LDGs in flight)
    const int s0 = src[(t        ) >> 2];
    const int s1 = src[(t +     T) >> 2];
    const int s2 = src[(t + 2 * T) >> 2];
    const int s3 = src[(t + 3 * T) >> 2];
    const int s4 = src[(t + 4 * T) >> 2];
    const int s5 = src[(t + 5 * T) >> 2];
    const int s6 = src[(t + 6 * T) >> 2];
    const int s7 = src[(t + 7 * T) >> 2];

    // Batch 0: gather + store
    {
        const float4 v0 = y4[s0 * 4 + ((t        ) & 3)];
        const float4 v1 = y4[s1 * 4 + ((t +     T) & 3)];
        const float4 v2 = y4[s2 * 4 + ((t + 2 * T) & 3)];
        const float4 v3 = y4[s3 * 4 + ((t + 3 * T) & 3)];
        out4[t        ] = v0;
        out4[t +     T] = v1;
        out4[t + 2 * T] = v2;
        out4[t + 3 * T] = v3;
    }
    // Batch 1: gather + store
    {
        const float4 v4 = y4[s4 * 4 + ((t + 4 * T) & 3)];
        const float4 v5 = y4[s5 * 4 + ((t + 5 * T) & 3)];
        const float4 v6 = y4[s6 * 4 + ((t + 6 * T) & 3)];
        const float4 v7 = y4[s7 * 4 + ((t + 7 * T) & 3)];
        out4[t + 4 * T] = v4;
        out4[t + 5 * T] = v5;
        out4[t + 6 * T] = v6;
        out4[t + 7 * T] = v7;
    }
}

// ---------------------------------------------------------------------------
extern "C" void kernel_launch(void* const* d_in, const int* in_sizes, int n_in,
                              void* d_out, int out_size) {
    const float* x     = (const float*)d_in[0];       // [N, 16] f32
    const float* extra = (const float*)d_in[1];       // [N, 16] f32
    const int* edge_index = (const int*)d_in[2];      // [2, E] int32 row-major

    int N = in_sizes[0] / FEAT;
    int E = in_sizes[2] / 2;
    const int* src = edge_index;                      // row 0 = edge_index[0]

    const int B = 256;

    // 1) histogram (E = 3.2M, divisible by 16). g_deg is zero on entry
    //    (module init on first call; reset by compute_y on every call).
    int E16 = E / 16;
    hist_kernel<<<(E16 + B - 1) / B, B>>>((const int4*)src, E16);

    // 2) per-node y = (deg-1)*x + extra, and reset deg for next call
    int n4 = N * (FEAT / 4);
    compute_y_kernel<<<(n4 + B - 1) / B, B>>>(
        (const float4*)x, (const float4*)extra, n4);

    // 3) gather: total = E*4 float4 elements, 8 per thread -> T = E/2
    int T = E / 2;
    gather_kernel<<<(T + B - 1) / B, B>>>(src, (float4*)d_out, T);
}

// round 8
// speedup vs baseline: 1.0803x; 1.0803x over previous
#include <cuda_runtime.h>
#include <cuda_bf16.h>
#include <cstdint>

#define N_NODES_MAX 100000
#define FEAT 16

__device__ int   g_deg[N_NODES_MAX];   // zero at load; every call re-zeros it in compute_y
__device__ float g_y[N_NODES_MAX * FEAT];

// ---------------------------------------------------------------------------
// Kernel 1: degree histogram. 4 edges per thread (one int4 load) -> 3125
// blocks, ~4x the warps of the 16/thread version so the LSU/LTS atomic
// queues stay full. Fire-and-forget atomics -> REDG.
// ---------------------------------------------------------------------------
__global__ void hist_kernel(const int4* __restrict__ src4, int E4) {
    int i = blockIdx.x * blockDim.x + threadIdx.x;
    if (i < E4) {
        int4 a = src4[i];
        atomicAdd(&g_deg[a.x], 1);
        atomicAdd(&g_deg[a.y], 1);
        atomicAdd(&g_deg[a.z], 1);
        atomicAdd(&g_deg[a.w], 1);
    }
}

// ---------------------------------------------------------------------------
// Kernel 2: per-node precompute  y[n] = (deg[n]-1)*x[n] + extra[n],
// and reset g_deg[n] = 0 for the next call. The 4 chunk-threads of a node
// form an aligned quad in one warp: read deg, __syncwarp, quad leader zeros.
// ---------------------------------------------------------------------------
__global__ void compute_y_kernel(const float4* __restrict__ x4,
                                 const float4* __restrict__ e4,
                                 int n4) {
    int i = blockIdx.x * blockDim.x + threadIdx.x;
    if (i < n4) {
        int node = i >> 2;
        int d = g_deg[node];
        __syncwarp();
        if ((i & 3) == 0) g_deg[node] = 0;
        float s = (float)(d - 1);
        float4 xv = x4[i];
        float4 ev = e4[i];
        float4 y;
        y.x = fmaf(s, xv.x, ev.x);
        y.y = fmaf(s, xv.y, ev.y);
        y.z = fmaf(s, xv.z, ev.z);
        y.w = fmaf(s, xv.w, ev.w);
        reinterpret_cast<float4*>(g_y)[i] = y;
    }
}

// ---------------------------------------------------------------------------
// Kernel 3: edge gather, ILP=4 (R3's exact proven form: 28 regs, no spill).
// Thread t owns elements {t + k*Q : k=0..3}, Q = total/4. 4 src loads ->
// 4 gather LDG.128 -> 4 STG.128, all coalesced.
// ---------------------------------------------------------------------------
__global__ void gather_kernel(const int* __restrict__ src,
                              float4* __restrict__ out4,
                              int Q /* = E*4/4 = E */) {
    int t = blockIdx.x * blockDim.x + threadIdx.x;
    if (t < Q) {
        const float4* __restrict__ y4 = reinterpret_cast<const float4*>(g_y);

        int i0 = t;
        int i1 = t + Q;
        int i2 = t + 2 * Q;
        int i3 = t + 3 * Q;
        int s0 = __ldg(&src[i0 >> 2]);
        int s1 = __ldg(&src[i1 >> 2]);
        int s2 = __ldg(&src[i2 >> 2]);
        int s3 = __ldg(&src[i3 >> 2]);

        float4 v0 = __ldg(&y4[s0 * 4 + (i0 & 3)]);
        float4 v1 = __ldg(&y4[s1 * 4 + (i1 & 3)]);
        float4 v2 = __ldg(&y4[s2 * 4 + (i2 & 3)]);
        float4 v3 = __ldg(&y4[s3 * 4 + (i3 & 3)]);

        out4[i0] = v0;
        out4[i1] = v1;
        out4[i2] = v2;
        out4[i3] = v3;
    }
}

// ---------------------------------------------------------------------------
extern "C" void kernel_launch(void* const* d_in, const int* in_sizes, int n_in,
                              void* d_out, int out_size) {
    const float* x     = (const float*)d_in[0];       // [N, 16] f32
    const float* extra = (const float*)d_in[1];       // [N, 16] f32
    const int* edge_index = (const int*)d_in[2];      // [2, E] int32 row-major

    int N = in_sizes[0] / FEAT;
    int E = in_sizes[2] / 2;
    const int* src = edge_index;                      // row 0 = edge_index[0]

    const int B = 256;

    // 1) histogram: 4 edges/thread (E divisible by 4)
    int E4 = E / 4;
    hist_kernel<<<(E4 + B - 1) / B, B>>>((const int4*)src, E4);

    // 2) per-node y = (deg-1)*x + extra, and reset deg for next call
    int n4 = N * (FEAT / 4);
    compute_y_kernel<<<(n4 + B - 1) / B, B>>>(
        (const float4*)x, (const float4*)extra, n4);

    // 3) gather: total = E*4 float4 elements, ILP=4 -> Q = E threads
    int Q = E;
    gather_kernel<<<(Q + B - 1) / B, B>>>(src, (float4*)d_out, Q);
}

// round 9
// speedup vs baseline: 1.0899x; 1.0089x over previous
#include <cuda_runtime.h>
#include <cuda_bf16.h>
#include <cstdint>

#define N_NODES_MAX 100000
#define FEAT 16

__device__ int   g_deg[N_NODES_MAX];   // zero at load; every call re-zeros it in compute_y
__device__ float g_y[N_NODES_MAX * FEAT];

// ---------------------------------------------------------------------------
// Kernel 1: degree histogram, 1 edge per thread. Maximizes the number of
// concurrent fire-and-forget REDG atomics in the LTS queues (the bound);
// the extra scalar loads are free (DRAM was at 8%).
// ---------------------------------------------------------------------------
__global__ void hist_kernel(const int* __restrict__ src, int E) {
    int i = blockIdx.x * blockDim.x + threadIdx.x;
    if (i < E) {
        atomicAdd(&g_deg[src[i]], 1);
    }
}

// ---------------------------------------------------------------------------
// Kernel 2: per-node precompute  y[n] = (deg[n]-1)*x[n] + extra[n],
// and reset g_deg[n] = 0 for the next call. The 4 chunk-threads of a node
// form an aligned quad in one warp: read deg, __syncwarp, quad leader zeros.
// ---------------------------------------------------------------------------
__global__ void compute_y_kernel(const float4* __restrict__ x4,
                                 const float4* __restrict__ e4,
                                 int n4) {
    int i = blockIdx.x * blockDim.x + threadIdx.x;
    if (i < n4) {
        int node = i >> 2;
        int d = g_deg[node];
        __syncwarp();
        if ((i & 3) == 0) g_deg[node] = 0;
        float s = (float)(d - 1);
        float4 xv = x4[i];
        float4 ev = e4[i];
        float4 y;
        y.x = fmaf(s, xv.x, ev.x);
        y.y = fmaf(s, xv.y, ev.y);
        y.z = fmaf(s, xv.z, ev.z);
        y.w = fmaf(s, xv.w, ev.w);
        reinterpret_cast<float4*>(g_y)[i] = y;
    }
}

// ---------------------------------------------------------------------------
// Kernel 3: edge gather, ILP=4 (R3's proven form: 28 regs, no spill).
// Thread t owns elements {t + k*Q : k=0..3}, Q = total/4. 4 src loads ->
// 4 gather LDG.128 -> 4 STG.128, all coalesced.
// ---------------------------------------------------------------------------
__global__ void gather_kernel(const int* __restrict__ src,
                              float4* __restrict__ out4,
                              int Q /* = E*4/4 = E */) {
    int t = blockIdx.x * blockDim.x + threadIdx.x;
    if (t < Q) {
        const float4* __restrict__ y4 = reinterpret_cast<const float4*>(g_y);

        int i0 = t;
        int i1 = t + Q;
        int i2 = t + 2 * Q;
        int i3 = t + 3 * Q;
        int s0 = __ldg(&src[i0 >> 2]);
        int s1 = __ldg(&src[i1 >> 2]);
        int s2 = __ldg(&src[i2 >> 2]);
        int s3 = __ldg(&src[i3 >> 2]);

        float4 v0 = __ldg(&y4[s0 * 4 + (i0 & 3)]);
        float4 v1 = __ldg(&y4[s1 * 4 + (i1 & 3)]);
        float4 v2 = __ldg(&y4[s2 * 4 + (i2 & 3)]);
        float4 v3 = __ldg(&y4[s3 * 4 + (i3 & 3)]);

        out4[i0] = v0;
        out4[i1] = v1;
        out4[i2] = v2;
        out4[i3] = v3;
    }
}

// ---------------------------------------------------------------------------
extern "C" void kernel_launch(void* const* d_in, const int* in_sizes, int n_in,
                              void* d_out, int out_size) {
    const float* x     = (const float*)d_in[0];       // [N, 16] f32
    const float* extra = (const float*)d_in[1];       // [N, 16] f32
    const int* edge_index = (const int*)d_in[2];      // [2, E] int32 row-major

    int N = in_sizes[0] / FEAT;
    int E = in_sizes[2] / 2;
    const int* src = edge_index;                      // row 0 = edge_index[0]

    const int B = 256;

    // 1) histogram: 1 edge/thread -> max outstanding atomics
    hist_kernel<<<(E + B - 1) / B, B>>>(src, E);

    // 2) per-node y = (deg-1)*x + extra, and reset deg for next call
    int n4 = N * (FEAT / 4);
    compute_y_kernel<<<(n4 + B - 1) / B, B>>>(
        (const float4*)x, (const float4*)extra, n4);

    // 3) gather: total = E*4 float4 elements, ILP=4 -> Q = E threads
    int Q = E;
    gather_kernel<<<(Q + B - 1) / B, B>>>(src, (float4*)d_out, Q);
}